// round 3
// baseline (speedup 1.0000x reference)
#include <cuda_runtime.h>
#include <cstdint>

#define NROWS 16384
#define DIN   4096
#define DOUT  4096
#define RNK   64
#define KTOP  8

#define DIN4  (DIN/4)    // 1024
#define DOUT4 (DOUT/4)   // 1024

#define NSPLIT 19
#define NPB ((NROWS + NSPLIT - 1)/NSPLIT)   // 863

// ---- scratch (no allocations allowed) ----
__device__ float4 g_G[NROWS*2];                  // gathered*scaled values, [n][8] as 2x float4
__device__ uint2  g_pidx[NROWS];                 // 8x 6-bit indices packed as bytes
__device__ __align__(16) float g_uwT[RNK*DOUT];  // up_w transposed to [64][4096]

// =====================================================================
// kT: transpose up_w [DOUT,RNK] -> g_uwT [RNK,DOUT]
// =====================================================================
__global__ void kT(const float* __restrict__ uw) {
    int o = blockIdx.x * 256 + threadIdx.x;   // 0..4095
    int r = blockIdx.y;                       // 0..63
    g_uwT[r * DOUT + o] = uw[o * RNK + r];    // coalesced store, strided L2 read (1MB total)
}

// =====================================================================
// kA: sparse down-projection. Block = 64 rows, warp = 8 rows.
// down_w staged in SMEM in [64][128] chunks.
// =====================================================================
__global__ __launch_bounds__(256, 2) void kA(
    const float* __restrict__ x, const float* __restrict__ dw,
    const float* __restrict__ tv, const long long* __restrict__ ti)
{
    __shared__ float4 Wsm[RNK * 32];   // [64 ranks][128 cols] floats = 32 KB
    __shared__ uint2  sidx[64];

    const int tid  = threadIdx.x;
    const int wid  = tid >> 5;
    const int lane = tid & 31;
    const int row0 = blockIdx.x * 64;

    // ---- sound dtype detection (in-bounds for BOTH int32 and int64 data) ----
    // If indices are int64 with values in [0,64), the high int32 word of each of
    // the first 8 elements is 0. If they are int32, positions 1,3,..,15 are real
    // distinct-per-row indices: at most 1 zero per row among them -> OR != 0.
    const int* t32base = (const int*)ti;
    const bool is64 = ((t32base[1] | t32base[3] | t32base[5] | t32base[7] |
                        t32base[9] | t32base[11] | t32base[13] | t32base[15]) == 0);

    // ---- pack top-k indices: lanes 0..7 of each warp handle one row each ----
    if (lane < 8) {
        int r   = wid * 8 + lane;
        int row = row0 + r;
        unsigned lo = 0, hi = 0;
        if (is64) {
            const long long* t64 = ti + (size_t)row * KTOP;
            #pragma unroll
            for (int k = 0; k < 4; k++) {
                lo |= ((unsigned)t64[k]     & 63u) << (8 * k);
                hi |= ((unsigned)t64[4 + k] & 63u) << (8 * k);
            }
        } else {
            const int* t32 = t32base + (size_t)row * KTOP;
            #pragma unroll
            for (int k = 0; k < 4; k++) {
                lo |= ((unsigned)t32[k]     & 63u) << (8 * k);
                hi |= ((unsigned)t32[4 + k] & 63u) << (8 * k);
            }
        }
        uint2 p; p.x = lo; p.y = hi;
        sidx[r]     = p;
        g_pidx[row] = p;
    }
    __syncthreads();

    uint2 pk[8];
    #pragma unroll
    for (int r8 = 0; r8 < 8; r8++) pk[r8] = sidx[wid * 8 + r8];

    float acc[8][8];
    #pragma unroll
    for (int i = 0; i < 8; i++)
        #pragma unroll
        for (int k = 0; k < 8; k++) acc[i][k] = 0.f;

    const float4* x4  = (const float4*)x;
    const float4* dw4 = (const float4*)dw;

    #pragma unroll 1
    for (int c = 0; c < DIN4 / 32; c++) {   // 32 chunks of 128 cols
        // cooperative load of down_w chunk (coalesced float4)
        #pragma unroll
        for (int t = 0; t < 8; t++) {
            int lin = tid + t * 256;                       // 0..2047 float4s
            Wsm[lin] = dw4[(lin >> 5) * DIN4 + c * 32 + (lin & 31)];
        }
        __syncthreads();

        #pragma unroll
        for (int r8 = 0; r8 < 8; r8++) {
            int row = row0 + wid * 8 + r8;
            float4 xv = x4[(size_t)row * DIN4 + c * 32 + lane];
            unsigned lo = pk[r8].x, hi = pk[r8].y;
            #pragma unroll
            for (int k = 0; k < 8; k++) {
                unsigned bits = (k < 4) ? lo : hi;
                unsigned idx  = (bits >> (8 * (k & 3))) & 63u;
                float4 wv = Wsm[idx * 32 + lane];          // uniform idx per warp -> conflict-free
                float a = acc[r8][k];
                a = fmaf(xv.x, wv.x, a);
                a = fmaf(xv.y, wv.y, a);
                a = fmaf(xv.z, wv.z, a);
                a = fmaf(xv.w, wv.w, a);
                acc[r8][k] = a;
            }
        }
        __syncthreads();
    }

    // ---- reduce across lanes, scale by top_k_values, store G ----
    #pragma unroll
    for (int r8 = 0; r8 < 8; r8++) {
        int row = row0 + wid * 8 + r8;
        #pragma unroll
        for (int k = 0; k < 8; k++) {
            float vsum = acc[r8][k];
            vsum += __shfl_xor_sync(0xffffffffu, vsum, 16);
            vsum += __shfl_xor_sync(0xffffffffu, vsum, 8);
            vsum += __shfl_xor_sync(0xffffffffu, vsum, 4);
            vsum += __shfl_xor_sync(0xffffffffu, vsum, 2);
            vsum += __shfl_xor_sync(0xffffffffu, vsum, 1);
            if (lane == k) {
                ((float*)g_G)[(size_t)row * KTOP + k] = vsum * tv[(size_t)row * KTOP + k];
            }
        }
    }
}

// =====================================================================
// kB: sparse up-projection. Block = 128-wide output tile (SMEM up_wT tile),
// warp = one row n per iteration, lane = 4 consecutive outputs.
// =====================================================================
__global__ __launch_bounds__(256) void kB(float* __restrict__ out)
{
    __shared__ float4 Usm[RNK * 32];   // [64 ranks][128 outs] floats = 32 KB

    const int tid  = threadIdx.x;
    const int wid  = tid >> 5;
    const int lane = tid & 31;
    const int ob4  = blockIdx.x * 32;         // float4 offset into DOUT4

    const float4* uwT4 = (const float4*)g_uwT;
    #pragma unroll
    for (int t = 0; t < 8; t++) {
        int lin = tid + t * 256;              // 0..2047
        Usm[lin] = uwT4[(lin >> 5) * DOUT4 + ob4 + (lin & 31)];
    }
    __syncthreads();

    float4* out4 = (float4*)out;

    int n    = blockIdx.y * NPB + wid;
    int nend = min((blockIdx.y + 1) * NPB, NROWS);
    if (n >= nend) return;

    uint2  p  = g_pidx[n];
    float4 Ga = g_G[n * 2];
    float4 Gb = g_G[n * 2 + 1];

    while (n < nend) {
        int n2 = n + 8;
        uint2 pn; float4 Gan, Gbn;
        if (n2 < nend) {                      // prefetch next row's metadata
            pn  = g_pidx[n2];
            Gan = g_G[n2 * 2];
            Gbn = g_G[n2 * 2 + 1];
        }

        float4 a; a.x = a.y = a.z = a.w = 0.f;
        float4 w;
        unsigned i0 =  p.x        & 63u;
        unsigned i1 = (p.x >> 8)  & 63u;
        unsigned i2 = (p.x >> 16) & 63u;
        unsigned i3 = (p.x >> 24) & 63u;
        unsigned i4 =  p.y        & 63u;
        unsigned i5 = (p.y >> 8)  & 63u;
        unsigned i6 = (p.y >> 16) & 63u;
        unsigned i7 = (p.y >> 24) & 63u;

        w = Usm[i0 * 32 + lane];
        a.x = fmaf(Ga.x, w.x, a.x); a.y = fmaf(Ga.x, w.y, a.y); a.z = fmaf(Ga.x, w.z, a.z); a.w = fmaf(Ga.x, w.w, a.w);
        w = Usm[i1 * 32 + lane];
        a.x = fmaf(Ga.y, w.x, a.x); a.y = fmaf(Ga.y, w.y, a.y); a.z = fmaf(Ga.y, w.z, a.z); a.w = fmaf(Ga.y, w.w, a.w);
        w = Usm[i2 * 32 + lane];
        a.x = fmaf(Ga.z, w.x, a.x); a.y = fmaf(Ga.z, w.y, a.y); a.z = fmaf(Ga.z, w.z, a.z); a.w = fmaf(Ga.z, w.w, a.w);
        w = Usm[i3 * 32 + lane];
        a.x = fmaf(Ga.w, w.x, a.x); a.y = fmaf(Ga.w, w.y, a.y); a.z = fmaf(Ga.w, w.z, a.z); a.w = fmaf(Ga.w, w.w, a.w);
        w = Usm[i4 * 32 + lane];
        a.x = fmaf(Gb.x, w.x, a.x); a.y = fmaf(Gb.x, w.y, a.y); a.z = fmaf(Gb.x, w.z, a.z); a.w = fmaf(Gb.x, w.w, a.w);
        w = Usm[i5 * 32 + lane];
        a.x = fmaf(Gb.y, w.x, a.x); a.y = fmaf(Gb.y, w.y, a.y); a.z = fmaf(Gb.y, w.z, a.z); a.w = fmaf(Gb.y, w.w, a.w);
        w = Usm[i6 * 32 + lane];
        a.x = fmaf(Gb.z, w.x, a.x); a.y = fmaf(Gb.z, w.y, a.y); a.z = fmaf(Gb.z, w.z, a.z); a.w = fmaf(Gb.z, w.w, a.w);
        w = Usm[i7 * 32 + lane];
        a.x = fmaf(Gb.w, w.x, a.x); a.y = fmaf(Gb.w, w.y, a.y); a.z = fmaf(Gb.w, w.z, a.z); a.w = fmaf(Gb.w, w.w, a.w);

        out4[(size_t)n * DOUT4 + ob4 + lane] = a;

        p = pn; Ga = Gan; Gb = Gbn; n = n2;
    }
}

// =====================================================================
extern "C" void kernel_launch(void* const* d_in, const int* in_sizes, int n_in,
                              void* d_out, int out_size)
{
    const float*     x  = (const float*)d_in[0];      // hidden_states [16384,4096]
    const float*     dw = (const float*)d_in[1];      // down_w [64,4096]
    const float*     uw = (const float*)d_in[2];      // up_w [4096,64]
    const float*     tv = (const float*)d_in[3];      // top_k_values [16384,8]
    const long long* ti = (const long long*)d_in[4];  // top_k_indices [16384,8] (i64 or i32, auto-detected)

    kT<<<dim3(DOUT / 256, RNK), 256>>>(uw);
    kA<<<NROWS / 64, 256>>>(x, dw, tv, ti);
    kB<<<dim3(DOUT / 128, NSPLIT), 256>>>((float*)d_out);
}